// round 11
// baseline (speedup 1.0000x reference)
#include <cuda_runtime.h>
#include <math.h>

// ---------------- problem constants ----------------
#define B32    32
#define TENC   256
#define TDEC   512
#define NMELS  80
#define EDIM   512
#define PRE    256
#define HID    1024
#define ATT    128
#define LOCF   32
#define LOCK   31
#define KA     1792           // PRE + EDIM + HID  (x | ctx | ah)
#define KD     2560           // HID + EDIM + HID  (ah | ctx | dh)
#define R4     4096
#define SPLT   4
#define NBLK   128
#define NTHR   256

#define MEL_SZ    (B32*NMELS*TDEC)
#define GATE_OFF  MEL_SZ
#define ALIGN_OFF (MEL_SZ + B32*TDEC)

// ---------------- static device buffers ----------------
__device__ float g_WaT[KA*R4];       // [k][r]
__device__ float g_WdT[KD*R4];       // [k][r]
__device__ float g_keys[B32*TENC*ATT];
__device__ float g_X[TDEC*B32*PRE];  // precomputed prenet outputs
__device__ float g_zp[SPLT*B32*R4];  // split-K partials
__device__ float g_Wqt[HID*ATT];
__device__ float g_Wmt[EDIM*ATT];
__device__ float g_Wp1t[NMELS*PRE];
__device__ float g_Wp2t[PRE*PRE];
__device__ float g_Wldt[LOCF*ATT];
__device__ float g_ba[R4];
__device__ float g_bd[R4];
__device__ float g_cat_a[B32*KA];    // [x | ctx | ah]
__device__ float g_cat_d[B32*KD];    // [ah | ctx | dh]
__device__ float g_ac[B32*HID];
__device__ float g_dc[B32*HID];
__device__ float g_aw[B32*TENC];
__device__ float g_awc[B32*TENC];
__device__ float g_q[B32*ATT];
__device__ float g_e[B32*TENC];

// grid barrier state (monotone epoch; works across graph replays without reset)
__device__ unsigned g_barcnt = 0;
__device__ volatile unsigned g_epoch = 0;

__device__ __forceinline__ float sigm(float x) { return 1.0f / (1.0f + expf(-x)); }
__device__ __forceinline__ unsigned rotl(unsigned x, int d) { return (x << d) | (x >> (32 - d)); }

__device__ __forceinline__ void gsync() {
    __syncthreads();
    if (threadIdx.x == 0) {
        __threadfence();
        unsigned e = g_epoch;
        if (atomicAdd(&g_barcnt, 1u) == NBLK - 1u) {
            g_barcnt = 0u;
            __threadfence();
            g_epoch = e + 1u;
        } else {
            while (g_epoch == e) { }
        }
        __threadfence();
    }
    __syncthreads();
}

// Bit-exact jax.random.bernoulli(jax.random.key(42), 0.5, (512,2,32,256)) * 2.0
// under the MODERN JAX default jax_threefry_partitionable=True:
//   per flat element i: threefry2x32 with key (0,42) applied to the 64-bit count
//   split as (hi, lo) = (0, i); the 32-bit random word is out_x0 XOR out_x1.
//   uniform = bitcast((bits>>9)|0x3F800000)-1;  uniform < 0.5  <=>  top bit clear.
__device__ float drop_mask(unsigned idx) {
    unsigned x0 = 0u, x1 = idx;
    const unsigned ks0 = 0u, ks1 = 42u, ks2 = 0x1BD11BDAu ^ 42u;
    x0 += ks0; x1 += ks1;
#define RND(r) { x0 += x1; x1 = rotl(x1, r); x1 ^= x0; }
    RND(13) RND(15) RND(26) RND(6)  x0 += ks1; x1 += ks2 + 1u;
    RND(17) RND(29) RND(16) RND(24) x0 += ks2; x1 += ks0 + 2u;
    RND(13) RND(15) RND(26) RND(6)  x0 += ks0; x1 += ks1 + 3u;
    RND(17) RND(29) RND(16) RND(24) x0 += ks1; x1 += ks2 + 4u;
    RND(13) RND(15) RND(26) RND(6)  x0 += ks2; x1 += ks0 + 5u;
#undef RND
    unsigned bits = x0 ^ x1;
    return (bits & 0x80000000u) ? 0.0f : 2.0f;
}

// ---------------- setup kernels ----------------
__global__ void k_zero() {
    int i = blockIdx.x * blockDim.x + threadIdx.x;
    int n = blockDim.x * gridDim.x;
    for (int idx = i; idx < B32*KA;   idx += n) g_cat_a[idx] = 0.f;
    for (int idx = i; idx < B32*KD;   idx += n) g_cat_d[idx] = 0.f;
    for (int idx = i; idx < B32*HID;  idx += n) { g_ac[idx] = 0.f; g_dc[idx] = 0.f; }
    for (int idx = i; idx < B32*TENC; idx += n) { g_aw[idx] = 0.f; g_awc[idx] = 0.f; }
}

// out[k][r] = (k < K1 ? in1[r][k] : in2[r][k-K1]);  K = K1+K2 total cols, R rows.
__global__ void k_concatT(float* __restrict__ out, const float* __restrict__ in1,
                          const float* __restrict__ in2, int K1, int K2, int R) {
    __shared__ float tile[32][33];
    int K = K1 + K2;
    int k = blockIdx.x * 32 + threadIdx.x;
    int r = blockIdx.y * 32 + threadIdx.y;
    float v = 0.f;
    if (k < K && r < R) v = (k < K1) ? in1[(size_t)r * K1 + k] : in2[(size_t)r * K2 + (k - K1)];
    tile[threadIdx.y][threadIdx.x] = v;
    __syncthreads();
    int ko = blockIdx.x * 32 + threadIdx.y;
    int ro = blockIdx.y * 32 + threadIdx.x;
    if (ko < K && ro < R) out[(size_t)ko * R + ro] = tile[threadIdx.x][threadIdx.y];
}

__global__ void k_bias(const float* bih_a, const float* bhh_a,
                       const float* bih_d, const float* bhh_d) {
    int i = blockIdx.x * blockDim.x + threadIdx.x;
    if (i < R4) { g_ba[i] = bih_a[i] + bhh_a[i]; g_bd[i] = bih_d[i] + bhh_d[i]; }
}

// keys[b][t][a] = sum_d memory[b][t][d] * Wm[a][d]   (Wm transposed -> g_Wmt[d][a])
__global__ void __launch_bounds__(128) k_keys(const float* __restrict__ memory) {
    int b = blockIdx.x, tc = blockIdx.y;
    __shared__ __align__(16) float sM[16 * EDIM];
    int t = threadIdx.x;
    for (int i = t; i < 16 * EDIM; i += 128) {
        int tt = i >> 9, d = i & 511;
        sM[i] = memory[((size_t)(b * TENC + tc * 16 + tt)) * EDIM + d];
    }
    __syncthreads();
    float acc[16];
#pragma unroll
    for (int j = 0; j < 16; j++) acc[j] = 0.f;
    int a = t;
    for (int d4 = 0; d4 < EDIM / 4; d4++) {
        float w0 = g_Wmt[(d4 * 4 + 0) * ATT + a];
        float w1 = g_Wmt[(d4 * 4 + 1) * ATT + a];
        float w2 = g_Wmt[(d4 * 4 + 2) * ATT + a];
        float w3 = g_Wmt[(d4 * 4 + 3) * ATT + a];
#pragma unroll
        for (int tt = 0; tt < 16; tt++) {
            float4 m = *(const float4*)&sM[tt * EDIM + d4 * 4];
            acc[tt] += m.x * w0 + m.y * w1 + m.z * w2 + m.w * w3;
        }
    }
    for (int tt = 0; tt < 16; tt++)
        g_keys[((size_t)(b * TENC + tc * 16 + tt)) * ATT + a] = acc[tt];
}

// Precompute prenet outputs for all 512 steps (teacher forcing + exact dropout).
__global__ void __launch_bounds__(256) k_prenet(const float* __restrict__ mel_target,
                                                const float* __restrict__ b_p1,
                                                const float* __restrict__ b_p2) {
    int t = blockIdx.x;      // decoder step
    int j = threadIdx.x;     // 256
    __shared__ __align__(16) float sDec[B32 * NMELS];
    __shared__ __align__(16) float sX1[B32 * PRE];
    for (int i = j; i < B32 * NMELS; i += 256) {
        int b = i / NMELS, m = i % NMELS;
        sDec[i] = (t == 0) ? 0.f : mel_target[((size_t)(b * NMELS + m)) * TDEC + (t - 1)];
    }
    __syncthreads();
    float acc[B32];
#pragma unroll
    for (int b = 0; b < B32; b++) acc[b] = 0.f;
    for (int m4 = 0; m4 < NMELS / 4; m4++) {
        float w0 = g_Wp1t[(4 * m4 + 0) * PRE + j];
        float w1 = g_Wp1t[(4 * m4 + 1) * PRE + j];
        float w2 = g_Wp1t[(4 * m4 + 2) * PRE + j];
        float w3 = g_Wp1t[(4 * m4 + 3) * PRE + j];
#pragma unroll
        for (int b = 0; b < B32; b++) {
            float4 d = *(const float4*)&sDec[b * NMELS + 4 * m4];
            acc[b] += d.x * w0 + d.y * w1 + d.z * w2 + d.w * w3;
        }
    }
    float bb = b_p1[j];
#pragma unroll
    for (int b = 0; b < B32; b++) {
        float v = acc[b] + bb; v = v > 0.f ? v : 0.f;
        v *= drop_mask(((unsigned)(t * 2 + 0) * B32 + b) * PRE + j);
        sX1[b * PRE + j] = v;
    }
    __syncthreads();
#pragma unroll
    for (int b = 0; b < B32; b++) acc[b] = 0.f;
    for (int k4 = 0; k4 < PRE / 4; k4++) {
        float w0 = g_Wp2t[(4 * k4 + 0) * PRE + j];
        float w1 = g_Wp2t[(4 * k4 + 1) * PRE + j];
        float w2 = g_Wp2t[(4 * k4 + 2) * PRE + j];
        float w3 = g_Wp2t[(4 * k4 + 3) * PRE + j];
#pragma unroll
        for (int b = 0; b < B32; b++) {
            float4 x = *(const float4*)&sX1[b * PRE + 4 * k4];
            acc[b] += x.x * w0 + x.y * w1 + x.z * w2 + x.w * w3;
        }
    }
    bb = b_p2[j];
#pragma unroll
    for (int b = 0; b < B32; b++) {
        float v = acc[b] + bb; v = v > 0.f ? v : 0.f;
        v *= drop_mask(((unsigned)(t * 2 + 1) * B32 + b) * PRE + j);
        g_X[((size_t)(t * B32 + b)) * PRE + j] = v;
    }
}

// ---------------- persistent-kernel phase bodies ----------------

// split-K GEMM: this block computes partials for (ntile, s) = (bx&31, bx>>5)
template <int K>
__device__ __forceinline__ void gemm_phase(const float* __restrict__ A,
                                           const float* __restrict__ W,
                                           const float* __restrict__ xptr, int XB,
                                           float* __restrict__ sh) {
    const int KC = K / SPLT;
    float* As = sh;           // [16][32]
    float* Ws = sh + 512;     // [16][128]
    int bx = blockIdx.x;
    int ntile = bx & 31, s = bx >> 5;
    int n0 = ntile * 128;
    int k0 = s * KC;
    int t = threadIdx.x;
    int bq = (t & 7) * 4;
    int nq = (t >> 3) * 4;
    float acc[4][4];
#pragma unroll
    for (int i = 0; i < 4; i++)
#pragma unroll
        for (int j = 0; j < 4; j++) acc[i][j] = 0.f;

    int lb = t >> 3;           // 0..31  (batch for A load)
    int lk2 = (t & 7) * 2;     // 0..14
    int lkk = t >> 4;          // 0..15  (k for W load)
    int ln8 = (t & 15) * 8;    // 0..120

    for (int it = 0; it < KC / 16; it++) {
        int kb = k0 + it * 16;
        {
            int kg = kb + lk2;
            const float* src = (kg < XB) ? (xptr + lb * XB + kg) : (A + lb * K + kg);
            float2 v = *(const float2*)src;
            As[lk2 * 32 + lb] = v.x; As[(lk2 + 1) * 32 + lb] = v.y;
        }
        {
            const float* src = W + (size_t)(kb + lkk) * R4 + n0 + ln8;
            float4 v0 = *(const float4*)src;
            float4 v1 = *(const float4*)(src + 4);
            *(float4*)&Ws[lkk * 128 + ln8] = v0;
            *(float4*)&Ws[lkk * 128 + ln8 + 4] = v1;
        }
        __syncthreads();
#pragma unroll
        for (int kk = 0; kk < 16; kk++) {
            float4 av = *(const float4*)&As[kk * 32 + bq];
            float4 wv = *(const float4*)&Ws[kk * 128 + nq];
            acc[0][0] += av.x * wv.x; acc[0][1] += av.x * wv.y; acc[0][2] += av.x * wv.z; acc[0][3] += av.x * wv.w;
            acc[1][0] += av.y * wv.x; acc[1][1] += av.y * wv.y; acc[1][2] += av.y * wv.z; acc[1][3] += av.y * wv.w;
            acc[2][0] += av.z * wv.x; acc[2][1] += av.z * wv.y; acc[2][2] += av.z * wv.z; acc[2][3] += av.z * wv.w;
            acc[3][0] += av.w * wv.x; acc[3][1] += av.w * wv.y; acc[3][2] += av.w * wv.z; acc[3][3] += av.w * wv.w;
        }
        __syncthreads();
    }
#pragma unroll
    for (int i = 0; i < 4; i++) {
        float4 v = make_float4(acc[i][0], acc[i][1], acc[i][2], acc[i][3]);
        *(float4*)&g_zp[((size_t)(s * B32 + bq + i)) * R4 + n0 + nq] = v;
    }
}

// combine attention-LSTM gates -> ah, ac; then q = ah @ Wq.T   (blocks 0..31)
__device__ __forceinline__ void combineA_phase(float* __restrict__ sh) {
    int b = blockIdx.x, t = threadIdx.x;
    float* sAh = sh;          // [1024]
    float* sQ = sh + 1024;    // [2][128]
#pragma unroll
    for (int u = 0; u < 4; u++) {
        int h = u * 256 + t;
        float zi = g_ba[h], zf = g_ba[HID + h], zg = g_ba[2 * HID + h], zo = g_ba[3 * HID + h];
#pragma unroll
        for (int s = 0; s < SPLT; s++) {
            const float* zp = &g_zp[((size_t)(s * B32 + b)) * R4];
            zi += zp[h]; zf += zp[HID + h]; zg += zp[2 * HID + h]; zo += zp[3 * HID + h];
        }
        float c = sigm(zf) * g_ac[b * HID + h] + sigm(zi) * tanhf(zg);
        float hn = sigm(zo) * tanhf(c);
        g_ac[b * HID + h] = c;
        sAh[h] = hn;
        g_cat_a[b * KA + 768 + h] = hn;
        g_cat_d[b * KD + h] = hn;
    }
    __syncthreads();
    int a = t & 127, half = t >> 7;
    float acc = 0.f;
    int j0 = half * 512;
    for (int j = 0; j < 512; j++)
        acc += sAh[j0 + j] * g_Wqt[(j0 + j) * ATT + a];
    sQ[half * ATT + a] = acc;
    __syncthreads();
    if (t < ATT) g_q[b * ATT + t] = sQ[t] + sQ[ATT + t];
}

// location conv + loc projection + tanh energies (masked) for a 64-t chunk (all 128 blocks)
__device__ __forceinline__ void att1_phase(const float* __restrict__ W_loc,
                                           const float* __restrict__ b_loc,
                                           const float* __restrict__ Wv,
                                           const int* __restrict__ mem_len,
                                           float* __restrict__ sh) {
    int bx = blockIdx.x;
    int b = bx & 31, tc = bx >> 5;
    int t = threadIdx.x;
    int tbase = tc * 64;
    float* sAw0 = sh;            // 96
    float* sAw1 = sh + 96;       // 96
    float* sQ   = sh + 192;      // 128
    float* sWl  = sh + 320;      // 1984
    float* sLoc = sh + 2304;     // 64*32
    float* sEp  = sh + 4352;     // 8*32
    if (t < ATT) sQ[t] = g_q[b * ATT + t];
    for (int i = t; i < 94; i += 256) {
        int tt = tbase - 15 + i;
        bool ok = (tt >= 0) && (tt < TENC);
        sAw0[i] = ok ? g_aw[b * TENC + tt] : 0.f;
        sAw1[i] = ok ? g_awc[b * TENC + tt] : 0.f;
    }
    for (int i = t; i < LOCF * 2 * LOCK; i += 256) sWl[i] = W_loc[i];
    __syncthreads();
    for (int i = t; i < 64 * LOCF; i += 256) {
        int f = i & 31, tt = i >> 5;
        float acc = b_loc[f];
        const float* w0 = &sWl[f * 62];
        const float* w1 = &sWl[f * 62 + 31];
#pragma unroll
        for (int k = 0; k < 31; k++)
            acc += sAw0[tt + k] * w0[k] + sAw1[tt + k] * w1[k];
        sLoc[tt * 32 + f] = acc;
    }
    __syncthreads();
    int a = t & 127;
    int half = t >> 7;                 // warps 0-3 -> tt 0..31, warps 4-7 -> tt 32..63
    float wld[32];
#pragma unroll
    for (int f = 0; f < 32; f++) wld[f] = g_Wldt[f * ATT + a];
    float wv = Wv[a];
    float qa = sQ[a];
    int lane = t & 31, w = t >> 5;
    for (int tl = 0; tl < 32; tl++) {
        int tt = half * 32 + tl;
        float lA = 0.f;
#pragma unroll
        for (int f = 0; f < 32; f++) lA += sLoc[tt * 32 + f] * wld[f];
        float v = tanhf(qa + g_keys[((size_t)(b * TENC + tbase + tt)) * ATT + a] + lA) * wv;
        for (int off = 16; off; off >>= 1) v += __shfl_down_sync(0xffffffffu, v, off);
        if (lane == 0) sEp[w * 32 + tl] = v;
    }
    __syncthreads();
    int L = mem_len[b];
    for (int tt = t; tt < 64; tt += 256) {
        float e;
        if (tt < 32) e = sEp[tt] + sEp[32 + tt] + sEp[64 + tt] + sEp[96 + tt];
        else { int tl = tt - 32; e = sEp[128 + tl] + sEp[160 + tl] + sEp[192 + tl] + sEp[224 + tl]; }
        int tg = tbase + tt;
        g_e[b * TENC + tg] = (tg >= L) ? -1e30f : e;
    }
}

// softmax -> aw, awc, alignments, ctx   (blocks 0..31)
__device__ __forceinline__ void att2_phase(const float* __restrict__ memory,
                                           float* __restrict__ dout, int tstep,
                                           float* __restrict__ sh) {
    int b = blockIdx.x, t = threadIdx.x;
    float* sE = sh;          // 256
    float* sR1 = sh + 256;   // 8
    float* sR2 = sh + 264;   // 8
    sE[t] = g_e[b * TENC + t];
    __syncthreads();
    float v = sE[t];
    for (int off = 16; off; off >>= 1) v = fmaxf(v, __shfl_down_sync(0xffffffffu, v, off));
    if ((t & 31) == 0) sR1[t >> 5] = v;
    __syncthreads();
    if (t < 8) {
        float m = sR1[t];
        for (int off = 4; off; off >>= 1) m = fmaxf(m, __shfl_down_sync(0xffu, m, off));
        if (t == 0) sR1[0] = m;
    }
    __syncthreads();
    float mx = sR1[0];
    float p = expf(sE[t] - mx);
    float sv = p;
    for (int off = 16; off; off >>= 1) sv += __shfl_down_sync(0xffffffffu, sv, off);
    if ((t & 31) == 0) sR2[t >> 5] = sv;
    __syncthreads();
    if (t < 8) {
        float m = sR2[t];
        for (int off = 4; off; off >>= 1) m += __shfl_down_sync(0xffu, m, off);
        if (t == 0) sR2[0] = m;
    }
    __syncthreads();
    float aw = p / sR2[0];
    __syncthreads();            // everyone done reading sE before overwrite
    sE[t] = aw;
    g_aw[b * TENC + t] = aw;
    g_awc[b * TENC + t] += aw;
    dout[ALIGN_OFF + ((size_t)(b * TDEC + tstep)) * TENC + t] = aw;
    __syncthreads();
    int d = t;
    float acc0 = 0.f, acc1 = 0.f;
    for (int tt = 0; tt < TENC; tt++) {
        float a = sE[tt];
        const float* mrow = &memory[((size_t)(b * TENC + tt)) * EDIM];
        acc0 += a * mrow[d];
        acc1 += a * mrow[d + 256];
    }
    g_cat_a[b * KA + 256 + d] = acc0;
    g_cat_a[b * KA + 256 + d + 256] = acc1;
    g_cat_d[b * KD + HID + d] = acc0;
    g_cat_d[b * KD + HID + d + 256] = acc1;
}

// combine decoder-LSTM gates -> dh, dc; then mel/gate projections   (blocks 0..31)
__device__ __forceinline__ void combineD_phase(const float* __restrict__ W_lin,
                                               const float* __restrict__ b_lin,
                                               const float* __restrict__ W_gate,
                                               const float* __restrict__ b_gate,
                                               float* __restrict__ dout, int tstep,
                                               float* __restrict__ sh) {
    int b = blockIdx.x, t = threadIdx.x;
    float* sOut = sh;        // [1536]
#pragma unroll
    for (int u = 0; u < 4; u++) {
        int h = u * 256 + t;
        float zi = g_bd[h], zf = g_bd[HID + h], zg = g_bd[2 * HID + h], zo = g_bd[3 * HID + h];
#pragma unroll
        for (int s = 0; s < SPLT; s++) {
            const float* zp = &g_zp[((size_t)(s * B32 + b)) * R4];
            zi += zp[h]; zf += zp[HID + h]; zg += zp[2 * HID + h]; zo += zp[3 * HID + h];
        }
        float c = sigm(zf) * g_dc[b * HID + h] + sigm(zi) * tanhf(zg);
        float hn = sigm(zo) * tanhf(c);
        g_dc[b * HID + h] = c;
        g_cat_d[b * KD + 1536 + h] = hn;
        sOut[h] = hn;
    }
    for (int i = t; i < EDIM; i += 256) sOut[HID + i] = g_cat_d[b * KD + HID + i];
    __syncthreads();
    int lane = t & 31, w = t >> 5;
    for (int m = w; m < 81; m += 8) {
        const float* row; float bias;
        if (m < 80) { row = W_lin + (size_t)m * 1536; bias = b_lin[m]; }
        else        { row = W_gate; bias = b_gate[0]; }
        float acc = 0.f;
        for (int k = lane; k < 1536; k += 32) acc += sOut[k] * row[k];
        for (int off = 16; off; off >>= 1) acc += __shfl_down_sync(0xffffffffu, acc, off);
        if (lane == 0) {
            float r = acc + bias;
            if (m < 80) dout[((size_t)(b * NMELS + m)) * TDEC + tstep] = r;
            else        dout[GATE_OFF + b * TDEC + tstep] = r;
        }
    }
}

// ---------------- the persistent 512-step kernel ----------------
__global__ void __launch_bounds__(NTHR) k_steps(const float* __restrict__ memory,
                                                const float* __restrict__ W_loc,
                                                const float* __restrict__ b_loc,
                                                const float* __restrict__ Wv,
                                                const int* __restrict__ mem_len,
                                                const float* __restrict__ W_lin,
                                                const float* __restrict__ b_lin,
                                                const float* __restrict__ W_gate,
                                                const float* __restrict__ b_gate,
                                                float* __restrict__ dout) {
    __shared__ __align__(16) float sh[4608];
    int bx = blockIdx.x;
    for (int t = 0; t < TDEC; t++) {
        // P1: attention-LSTM gate GEMM (all 128 blocks)
        gemm_phase<KA>(g_cat_a, g_WaT, g_X + (size_t)t * B32 * PRE, PRE, sh);
        gsync();
        // P2: attention-LSTM activation + q projection
        if (bx < 32) combineA_phase(sh);
        gsync();
        // P3: location conv + energies (all 128 blocks: 32 b x 4 chunks)
        att1_phase(W_loc, b_loc, Wv, mem_len, sh);
        gsync();
        // P4: softmax + context
        if (bx < 32) att2_phase(memory, dout, t, sh);
        gsync();
        // P5: decoder-LSTM gate GEMM (all 128 blocks)
        gemm_phase<KD>(g_cat_d, g_WdT, (const float*)0, 0, sh);
        gsync();
        // P6: decoder-LSTM activation + mel/gate projections
        if (bx < 32) combineD_phase(W_lin, b_lin, W_gate, b_gate, dout, t, sh);
        gsync();
    }
}

// ---------------- host ----------------
extern "C" void kernel_launch(void* const* d_in, const int* in_sizes, int n_in,
                              void* d_out, int out_size) {
    const float* memory   = (const float*)d_in[0];
    const float* mel_tgt  = (const float*)d_in[1];
    const int*   mem_len  = (const int*)  d_in[2];
    const float* W_p1     = (const float*)d_in[3];
    const float* b_p1     = (const float*)d_in[4];
    const float* W_p2     = (const float*)d_in[5];
    const float* b_p2     = (const float*)d_in[6];
    const float* Wih_a    = (const float*)d_in[7];
    const float* Whh_a    = (const float*)d_in[8];
    const float* bih_a    = (const float*)d_in[9];
    const float* bhh_a    = (const float*)d_in[10];
    const float* Wq       = (const float*)d_in[11];
    const float* Wm       = (const float*)d_in[12];
    const float* Wv       = (const float*)d_in[13];
    const float* W_loc    = (const float*)d_in[14];
    const float* b_loc    = (const float*)d_in[15];
    const float* W_locd   = (const float*)d_in[16];
    const float* Wih_d    = (const float*)d_in[17];
    const float* Whh_d    = (const float*)d_in[18];
    const float* bih_d    = (const float*)d_in[19];
    const float* bhh_d    = (const float*)d_in[20];
    const float* W_lin    = (const float*)d_in[21];
    const float* b_lin    = (const float*)d_in[22];
    const float* W_gate   = (const float*)d_in[23];
    const float* b_gate   = (const float*)d_in[24];
    float* out = (float*)d_out;

    float *WaT, *WdT, *Wqt, *Wmt, *Wp1t, *Wp2t, *Wldt;
    cudaGetSymbolAddress((void**)&WaT,  g_WaT);
    cudaGetSymbolAddress((void**)&WdT,  g_WdT);
    cudaGetSymbolAddress((void**)&Wqt,  g_Wqt);
    cudaGetSymbolAddress((void**)&Wmt,  g_Wmt);
    cudaGetSymbolAddress((void**)&Wp1t, g_Wp1t);
    cudaGetSymbolAddress((void**)&Wp2t, g_Wp2t);
    cudaGetSymbolAddress((void**)&Wldt, g_Wldt);

    dim3 tb(32, 32);
    k_zero<<<256, 256>>>();
    k_concatT<<<dim3(KA / 32, R4 / 32), tb>>>(WaT, Wih_a, Whh_a, 768, 1024, R4);
    k_concatT<<<dim3(KD / 32, R4 / 32), tb>>>(WdT, Wih_d, Whh_d, 1536, 1024, R4);
    k_concatT<<<dim3(32, 4),  tb>>>(Wqt,  Wq,     Wq,     1024, 0, 128);  // [1024][128]
    k_concatT<<<dim3(16, 4),  tb>>>(Wmt,  Wm,     Wm,     512,  0, 128);  // [512][128]
    k_concatT<<<dim3(3, 8),   tb>>>(Wp1t, W_p1,   W_p1,   80,   0, 256);  // [80][256]
    k_concatT<<<dim3(8, 8),   tb>>>(Wp2t, W_p2,   W_p2,   256,  0, 256);  // [256][256]
    k_concatT<<<dim3(1, 4),   tb>>>(Wldt, W_locd, W_locd, 32,   0, 128);  // [32][128]
    k_bias<<<16, 256>>>(bih_a, bhh_a, bih_d, bhh_d);
    k_keys<<<dim3(32, 16), 128>>>(memory);
    k_prenet<<<512, 256>>>(mel_tgt, b_p1, b_p2);

    k_steps<<<NBLK, NTHR>>>(memory, W_loc, b_loc, Wv, mem_len,
                            W_lin, b_lin, W_gate, b_gate, out);
}